// round 1
// baseline (speedup 1.0000x reference)
#include <cuda_runtime.h>
#include <math.h>

#define B 4096
#define D 256
#define NREG 4
#define NT 32          // B / BMT tiles per dim
#define BMT 128        // CTA tile (rows == cols)
#define BKT 16         // K tile

// ---------------- scratch (no allocations allowed) ----------------
__device__ __align__(16) float g_Ps[B * D];   // normalized projections, label-sorted
__device__ int   g_src[B];                    // sorted idx -> original idx
__device__ int   g_n0;                        // count of label==0 (first group)
__device__ float g_RP[B * NT];                // per-(row, col-tile) partial sum of exp over neg
__device__ float g_L[B];                      // neg logsumexp per sorted row
__device__ float g_part2[NT * NT];            // per-CTA partial pos sums
__device__ float g_part_focal[16];
__device__ float g_part_region[32 * 16];      // per block: 6 pd-pairs, 6 ct-pairs, 4 ce

// ---------------- f32x2 packed FMA helpers ----------------
__device__ __forceinline__ unsigned long long pk2(float lo, float hi) {
    unsigned long long r;
    asm("mov.b64 %0, {%1,%2};" : "=l"(r) : "f"(lo), "f"(hi));
    return r;
}
__device__ __forceinline__ void upk2(unsigned long long v, float& lo, float& hi) {
    asm("mov.b64 {%0,%1}, %2;" : "=f"(lo), "=f"(hi) : "l"(v));
}
__device__ __forceinline__ void ffma2(unsigned long long& d, unsigned long long a, unsigned long long b) {
    asm("fma.rn.f32x2 %0, %1, %2, %0;" : "+l"(d) : "l"(a), "l"(b));
}

// ---------------- 1. stable partition by label (single block scan) ----------------
__global__ void k_scan(const int* __restrict__ labels) {
    __shared__ int sd[1024];
    int t = threadIdx.x;            // 1024 threads, 4 labels each
    int base = t * 4;
    int z[4]; int cnt = 0;
#pragma unroll
    for (int u = 0; u < 4; u++) { z[u] = (labels[base + u] == 0) ? 1 : 0; cnt += z[u]; }
    sd[t] = cnt;
    __syncthreads();
    for (int off = 1; off < 1024; off <<= 1) {
        int v = (t >= off) ? sd[t - off] : 0;
        __syncthreads();
        sd[t] += v;
        __syncthreads();
    }
    int n0 = sd[1023];
    int zb = sd[t] - cnt;           // zeros strictly before this thread's first element
#pragma unroll
    for (int u = 0; u < 4; u++) {
        int i = base + u, dest;
        if (z[u]) { dest = zb; zb++; }
        else      { dest = n0 + (i - zb); }
        g_src[dest] = i;
    }
    if (t == 0) g_n0 = n0;
}

// ---------------- 2. gather + L2-normalize rows (1 warp per row) ----------------
__global__ void k_norm(const float* __restrict__ proj) {
    int warp = (blockIdx.x * blockDim.x + threadIdx.x) >> 5;
    int lane = threadIdx.x & 31;
    if (warp >= B) return;
    int src = g_src[warp];
    const float* row = proj + src * D;
    float v[8]; float ss = 0.f;
#pragma unroll
    for (int u = 0; u < 8; u++) { v[u] = row[lane + u * 32]; ss += v[u] * v[u]; }
#pragma unroll
    for (int o = 16; o > 0; o >>= 1) ss += __shfl_xor_sync(0xffffffffu, ss, o);
    float nrm = fmaxf(sqrtf(ss), 1e-12f);
    float inv = 1.0f / nrm;
    float* out = g_Ps + warp * D;
#pragma unroll
    for (int u = 0; u < 8; u++) out[lane + u * 32] = v[u] * inv;
}

// ---------------- 3. zero RP partials ----------------
__global__ void k_zero() {
    int i = blockIdx.x * blockDim.x + threadIdx.x;
    if (i < B * NT) g_RP[i] = 0.f;
}

// ---------------- shared 128x128x256 fp32 tile GEMM (FFMA2 mainloop) ----------------
__device__ __forceinline__ void mma_tile(int row0, int col0,
                                         float (*As)[BMT], float (*Bs)[BMT],
                                         unsigned long long (*acc)[4]) {
    int t = threadIdx.x, tx = t & 15, ty = t >> 4;
#pragma unroll
    for (int i = 0; i < 8; i++)
#pragma unroll
        for (int j = 0; j < 4; j++) acc[i][j] = 0ull;

    for (int kk = 0; kk < D; kk += BKT) {
        __syncthreads();                         // WAR from previous iteration
#pragma unroll
        for (int u = 0; u < 2; u++) {            // 512 float4 per tile, 2 per thread
            int idx = t + 256 * u;
            int r = idx >> 2, kq = idx & 3;
            float4 va = *reinterpret_cast<const float4*>(&g_Ps[(row0 + r) * D + kk + kq * 4]);
            As[kq * 4 + 0][r] = va.x; As[kq * 4 + 1][r] = va.y;
            As[kq * 4 + 2][r] = va.z; As[kq * 4 + 3][r] = va.w;
            float4 vb = *reinterpret_cast<const float4*>(&g_Ps[(col0 + r) * D + kk + kq * 4]);
            Bs[kq * 4 + 0][r] = vb.x; Bs[kq * 4 + 1][r] = vb.y;
            Bs[kq * 4 + 2][r] = vb.z; Bs[kq * 4 + 3][r] = vb.w;
        }
        __syncthreads();
#pragma unroll
        for (int k = 0; k < BKT; k++) {
            float a[8], b[8];
            *reinterpret_cast<float4*>(&a[0]) = *reinterpret_cast<const float4*>(&As[k][ty * 8]);
            *reinterpret_cast<float4*>(&a[4]) = *reinterpret_cast<const float4*>(&As[k][ty * 8 + 4]);
            *reinterpret_cast<float4*>(&b[0]) = *reinterpret_cast<const float4*>(&Bs[k][tx * 8]);
            *reinterpret_cast<float4*>(&b[4]) = *reinterpret_cast<const float4*>(&Bs[k][tx * 8 + 4]);
            unsigned long long b2[4];
#pragma unroll
            for (int j = 0; j < 4; j++) b2[j] = pk2(b[2 * j], b[2 * j + 1]);
#pragma unroll
            for (int i = 0; i < 8; i++) {
                unsigned long long a2 = pk2(a[i], a[i]);
#pragma unroll
                for (int j = 0; j < 4; j++) ffma2(acc[i][j], a2, b2[j]);
            }
        }
    }
    __syncthreads();   // allow caller to reuse As/Bs
}

// ---------------- 4. cross block: sum of exp(sim) over neg pairs ----------------
// rows r < n0 (G0), cols c >= n0 (G1). Symmetric: row-sums feed L of G0,
// col-sums feed L of G1. Deterministic: unique (row, tile) slot per CTA.
__global__ void __launch_bounds__(256) k_cross() {
    __shared__ float As[BKT][BMT];
    __shared__ float Bs[BKT][BMT];
    int by = blockIdx.y, bx = blockIdx.x;
    int row0 = by * BMT, col0 = bx * BMT;
    int n0 = g_n0;
    if (!(row0 < n0 && col0 + BMT - 1 >= n0)) return;

    unsigned long long acc[8][4];
    mma_tile(row0, col0, As, Bs, acc);

    int t = threadIdx.x, tx = t & 15, ty = t >> 4;
    float rowl[8], coll[8];
#pragma unroll
    for (int i = 0; i < 8; i++) { rowl[i] = 0.f; coll[i] = 0.f; }
#pragma unroll
    for (int i = 0; i < 8; i++) {
        int r = row0 + ty * 8 + i;
        bool rok = (r < n0);
#pragma unroll
        for (int j = 0; j < 4; j++) {
            float s0, s1; upk2(acc[i][j], s0, s1);
            int c0 = col0 + tx * 8 + 2 * j;
            float e0 = (rok && (c0     >= n0)) ? expf(s0 * 10.0f) : 0.0f;  // /TEMP
            float e1 = (rok && (c0 + 1 >= n0)) ? expf(s1 * 10.0f) : 0.0f;
            rowl[i] += e0 + e1;
            coll[2 * j] += e0; coll[2 * j + 1] += e1;
        }
    }
    float (*rowp)[BMT] = As;   // reuse smem for deterministic reductions
    float (*colp)[BMT] = Bs;
#pragma unroll
    for (int i = 0; i < 8; i++) rowp[tx][ty * 8 + i] = rowl[i];
#pragma unroll
    for (int j = 0; j < 8; j++) colp[ty][tx * 8 + j] = coll[j];
    __syncthreads();
    if (t < BMT) {
        float rs = 0.f, cs = 0.f;
#pragma unroll
        for (int q = 0; q < 16; q++) { rs += rowp[q][t]; cs += colp[q][t]; }
        int r = row0 + t, c = col0 + t;
        if (r < n0)  g_RP[r * NT + bx] = rs;
        if (c >= n0) g_RP[c * NT + by] = cs;
    }
}

// ---------------- 5. L[i] = log(sum of partials) ----------------
__global__ void k_L() {
    int i = blockIdx.x * blockDim.x + threadIdx.x;
    float s = 0.f;
#pragma unroll
    for (int q = 0; q < NT; q++) s += g_RP[i * NT + q];
    g_L[i] = logf(s);
}

// ---------------- 6. within blocks: sum softplus(L - sim) over pos pairs ----------
// only tm <= tn tiles; off-diagonal tiles emit both orientations via symmetry.
__global__ void __launch_bounds__(256) k_within() {
    __shared__ float As[BKT][BMT];
    __shared__ float Bs[BKT][BMT];
    __shared__ float red[256];
    int by = blockIdx.y, bx = blockIdx.x;
    int pidx = by * NT + bx;
    int n0 = g_n0;
    int row0 = by * BMT, col0 = bx * BMT;
    bool active = (bx >= by) && !(row0 + BMT - 1 < n0 && col0 >= n0);
    if (!active) { if (threadIdx.x == 0) g_part2[pidx] = 0.f; return; }

    unsigned long long acc[8][4];
    mma_tile(row0, col0, As, Bs, acc);

    int t = threadIdx.x, tx = t & 15, ty = t >> 4;
    float Lr[8], Lc[8];
#pragma unroll
    for (int i = 0; i < 8; i++) Lr[i] = g_L[row0 + ty * 8 + i];
#pragma unroll
    for (int j = 0; j < 8; j++) Lc[j] = g_L[col0 + tx * 8 + j];
    bool offdiag = (bx != by);
    float local = 0.f;
#pragma unroll
    for (int i = 0; i < 8; i++) {
        int r = row0 + ty * 8 + i;
        bool gr = (r >= n0);
#pragma unroll
        for (int j = 0; j < 4; j++) {
            float s0, s1; upk2(acc[i][j], s0, s1);
#pragma unroll
            for (int h = 0; h < 2; h++) {
                float sv = h ? s1 : s0;
                int jj = 2 * j + h;
                int c = col0 + tx * 8 + jj;
                bool gc = (c >= n0);
                if (gr == gc && r != c) {
                    float s = sv * 10.0f;                       // /TEMP
                    local += logf(1.0f + expf(Lr[i] - s));      // pair (r,c)
                    if (offdiag)
                        local += logf(1.0f + expf(Lc[jj] - s)); // pair (c,r)
                }
            }
        }
    }
    red[t] = local; __syncthreads();
    for (int off = 128; off > 0; off >>= 1) { if (t < off) red[t] += red[t + off]; __syncthreads(); }
    if (t == 0) g_part2[pidx] = red[0];
}

// ---------------- 7. focal loss partials ----------------
__global__ void k_focal(const float* __restrict__ logits, const int* __restrict__ labels) {
    __shared__ float red[256];
    int t = threadIdx.x;
    int i = blockIdx.x * 256 + t;
    float z0 = logits[2 * i] / 1.5f;
    float z1 = logits[2 * i + 1] / 1.5f;
    float m = fmaxf(z0, z1);
    float lse = m + logf(expf(z0 - m) + expf(z1 - m));
    float ce = lse - (labels[i] ? z1 : z0);
    float pt = expf(-ce);
    float om = 1.0f - pt;
    red[t] = om * om * ce;
    __syncthreads();
    for (int off = 128; off > 0; off >>= 1) { if (t < off) red[t] += red[t + off]; __syncthreads(); }
    if (t == 0) g_part_focal[blockIdx.x] = red[0];
}

// ---------------- 8. region loss partials ----------------
__global__ void k_region(const float* __restrict__ rp, const int* __restrict__ labels) {
    __shared__ float red[16][128];
    int t = threadIdx.x;                // 128 threads, 32 blocks
    int b = blockIdx.x * 128 + t;
    float acc[16];
#pragma unroll
    for (int k = 0; k < 16; k++) acc[k] = 0.f;
    {
        int lab = labels[b];
        float p[4][2], lp[4][2], lpe[4][2], ent[4];
#pragma unroll
        for (int i = 0; i < 4; i++) {
            float x0 = rp[(i * B + b) * 2 + 0];
            float x1 = rp[(i * B + b) * 2 + 1];
            float m = fmaxf(x0, x1);
            float lse = m + logf(expf(x0 - m) + expf(x1 - m));
            lp[i][0] = x0 - lse; lp[i][1] = x1 - lse;
            p[i][0] = expf(lp[i][0]); p[i][1] = expf(lp[i][1]);
            lpe[i][0] = logf(p[i][0] + 1e-10f);
            lpe[i][1] = logf(p[i][1] + 1e-10f);
            ent[i] = p[i][0] * lp[i][0] + p[i][1] * lp[i][1];
            acc[12 + i] += -(lab ? lp[i][1] : lp[i][0]);   // CE
        }
        int pi = 0;
#pragma unroll
        for (int i = 0; i < 4; i++)
#pragma unroll
            for (int j = i + 1; j < 4; j++, pi++) {
                float kl = ent[j] - (p[j][0] * lpe[i][0] + p[j][1] * lpe[i][1]);
                if (lab) acc[pi] += kl; else acc[6 + pi] += kl;
            }
    }
#pragma unroll
    for (int k = 0; k < 16; k++) red[k][t] = acc[k];
    __syncthreads();
    for (int off = 64; off > 0; off >>= 1) {
        if (t < off) {
#pragma unroll
            for (int k = 0; k < 16; k++) red[k][t] += red[k][t + off];
        }
        __syncthreads();
    }
    if (t < 16) g_part_region[blockIdx.x * 16 + t] = red[t][0];
}

// ---------------- 9. final combine ----------------
__global__ void k_final(float* __restrict__ out) {
    __shared__ float red[256];
    __shared__ float sreg[16];
    __shared__ float sfoc;
    int t = threadIdx.x;
    float s = 0.f;
    for (int i = t; i < NT * NT; i += 256) s += g_part2[i];
    red[t] = s; __syncthreads();
    for (int off = 128; off > 0; off >>= 1) { if (t < off) red[t] += red[t + off]; __syncthreads(); }
    if (t < 16) {
        float a = 0.f;
        for (int blk = 0; blk < 32; blk++) a += g_part_region[blk * 16 + t];
        sreg[t] = a;
    }
    if (t == 16) {
        float f = 0.f;
        for (int i = 0; i < 16; i++) f += g_part_focal[i];
        sfoc = f;
    }
    __syncthreads();
    if (t == 0) {
        int n0 = g_n0;
        float cont = red[0] / (float)B;
        float foc = sfoc / (float)B;
        float pd = (float)(B - n0), ct = (float)n0;
        float rl = 0.f;
        for (int pi = 0; pi < 6; pi++) {
            float kpd = (pd > 0.f) ? sreg[pi]     / fmaxf(pd, 1.f) : 0.f;
            float kct = (ct > 0.f) ? sreg[6 + pi] / fmaxf(ct, 1.f) : 0.f;
            rl += kpd + kct;
        }
        for (int i = 0; i < 4; i++) rl += sreg[12 + i] / (float)B;
        rl /= 10.0f;                     // R*(R-1)/2 + R = 6 + 4
        out[0] = foc + 0.5f * cont + 0.3f * rl;
    }
}

// ---------------- launch ----------------
extern "C" void kernel_launch(void* const* d_in, const int* in_sizes, int n_in,
                              void* d_out, int out_size) {
    const float* logits = nullptr;
    const float* proj   = nullptr;
    const float* rp     = nullptr;
    const int*   labels = nullptr;
    for (int i = 0; i < n_in; i++) {        // identify by element count (all distinct)
        switch (in_sizes[i]) {
            case B * 2:        logits = (const float*)d_in[i]; break;
            case B * D:        proj   = (const float*)d_in[i]; break;
            case NREG * B * 2: rp     = (const float*)d_in[i]; break;
            case B:            labels = (const int*)d_in[i];   break;
        }
    }
    k_zero<<<512, 256>>>();
    k_scan<<<1, 1024>>>(labels);
    k_norm<<<512, 256>>>(proj);
    dim3 g(NT, NT);
    k_cross<<<g, 256>>>();
    k_L<<<16, 256>>>();
    k_within<<<g, 256>>>();
    k_focal<<<16, 256>>>(logits, labels);
    k_region<<<32, 128>>>(rp, labels);
    k_final<<<1, 256>>>((float*)d_out);
}

// round 4
// speedup vs baseline: 2.0682x; 2.0682x over previous
#include <cuda_runtime.h>
#include <cstdint>
#include <math.h>

#define B 4096
#define D 256
#define NT 32              // 128-wide tile count per dim
#define SMEM_BYTES 73728   // 2 x (A 128x36 + B 128x36) floats

// ---------------- scratch (no allocations allowed) ----------------
__device__ __align__(16) float g_Ps[B * D];   // normalized projections (tf32-rounded), label-sorted
__device__ int   g_src[B];
__device__ int   g_n0;
__device__ float g_RP[B * NT];                // per-(row, col-tile) partial exp sums over negatives
__device__ float g_L[B];
__device__ float g_part2[NT * NT];
__device__ float g_part_focal[16];
__device__ float g_part_region[32 * 16];

// ---------------- helpers ----------------
__device__ __forceinline__ uint32_t smem_u32(const void* p) {
    uint32_t a;
    asm("{ .reg .u64 t; cvta.to.shared.u64 t, %1; cvt.u32.u64 %0, t; }" : "=r"(a) : "l"(p));
    return a;
}
__device__ __forceinline__ void cp16(uint32_t d, const void* s) {
    asm volatile("cp.async.cg.shared.global [%0], [%1], 16;" :: "r"(d), "l"(s));
}
__device__ __forceinline__ void cp_commit() { asm volatile("cp.async.commit_group;" ::: "memory"); }
__device__ __forceinline__ void cp_wait1()  { asm volatile("cp.async.wait_group 1;" ::: "memory"); }
__device__ __forceinline__ void cp_wait0()  { asm volatile("cp.async.wait_group 0;" ::: "memory"); }
__device__ __forceinline__ float round_tf32(float x) {
    float r;
    asm("cvt.rna.tf32.f32 %0, %1;" : "=f"(r) : "f"(x));
    return r;
}

// ---------------- 128x128x256 tf32 tile GEMM via mma.sync, acc in registers ----------------
// 256 threads = 8 warps arranged 4(m) x 2(n); warp tile 32x64; per-warp 2x8 m16n8k8 tiles.
// Per thread: acc[mt][nt][4]; element map (lane l, g=l>>2, tg=l&3):
//   c0:(row mt*16+g, col nt*8+tg*2) c1:(+0,+1) c2:(row+8,+0) c3:(row+8,+1)
__device__ __forceinline__ void gemm_tile(char* sm, uint32_t sb, int row0, int col0,
                                          float (*acc)[8][4]) {
    int t = threadIdx.x;
    int w = t >> 5, l = t & 31;
    int wm = w & 3, wn = w >> 1 & 0 ? 0 : (w >> 2);   // wn = w>>2
    int g = l >> 2, tg = l & 3;
#pragma unroll
    for (int mt = 0; mt < 2; mt++)
#pragma unroll
        for (int nt = 0; nt < 8; nt++)
#pragma unroll
            for (int e = 0; e < 4; e++) acc[mt][nt][e] = 0.f;

    // prefetch chunk 0
#pragma unroll
    for (int u = 0; u < 4; u++) {
        int idx = t + 256 * u, r = idx >> 3, q = idx & 7;
        uint32_t so = (uint32_t)(r * 36 + q * 4) * 4u;
        cp16(sb + so, &g_Ps[(row0 + r) * D + q * 4]);
        cp16(sb + 18432u + so, &g_Ps[(col0 + r) * D + q * 4]);
    }
    cp_commit();

    for (int c = 0; c < 8; c++) {
        uint32_t pb = (uint32_t)(c & 1) * 36864u;
        if (c < 7) {
            uint32_t nb = (uint32_t)((c + 1) & 1) * 36864u;
            int kk = (c + 1) * 32;
#pragma unroll
            for (int u = 0; u < 4; u++) {
                int idx = t + 256 * u, r = idx >> 3, q = idx & 7;
                uint32_t so = (uint32_t)(r * 36 + q * 4) * 4u;
                cp16(sb + nb + so, &g_Ps[(row0 + r) * D + kk + q * 4]);
                cp16(sb + nb + 18432u + so, &g_Ps[(col0 + r) * D + kk + q * 4]);
            }
            cp_commit();
            cp_wait1();
        } else {
            cp_wait0();
        }
        __syncthreads();
        const float* Asm = (const float*)(sm + pb);
        const float* Bsm = (const float*)(sm + pb + 18432);
#pragma unroll
        for (int ks = 0; ks < 4; ks++) {
            int k0 = ks * 8;
            uint32_t a[2][4], b[8][2];
#pragma unroll
            for (int mt = 0; mt < 2; mt++) {
                int ar = wm * 32 + mt * 16 + g;
                a[mt][0] = __float_as_uint(Asm[ar * 36 + k0 + tg]);
                a[mt][1] = __float_as_uint(Asm[(ar + 8) * 36 + k0 + tg]);
                a[mt][2] = __float_as_uint(Asm[ar * 36 + k0 + tg + 4]);
                a[mt][3] = __float_as_uint(Asm[(ar + 8) * 36 + k0 + tg + 4]);
            }
#pragma unroll
            for (int nt = 0; nt < 8; nt++) {
                int br = wn * 64 + nt * 8 + g;
                b[nt][0] = __float_as_uint(Bsm[br * 36 + k0 + tg]);
                b[nt][1] = __float_as_uint(Bsm[br * 36 + k0 + tg + 4]);
            }
#pragma unroll
            for (int mt = 0; mt < 2; mt++)
#pragma unroll
                for (int nt = 0; nt < 8; nt++)
                    asm volatile(
                        "mma.sync.aligned.m16n8k8.row.col.f32.tf32.tf32.f32 "
                        "{%0,%1,%2,%3}, {%4,%5,%6,%7}, {%8,%9}, {%0,%1,%2,%3};"
                        : "+f"(acc[mt][nt][0]), "+f"(acc[mt][nt][1]),
                          "+f"(acc[mt][nt][2]), "+f"(acc[mt][nt][3])
                        : "r"(a[mt][0]), "r"(a[mt][1]), "r"(a[mt][2]), "r"(a[mt][3]),
                          "r"(b[nt][0]), "r"(b[nt][1]));
        }
        __syncthreads();
    }
}

// ---------------- 1. stable partition by label ----------------
__global__ void k_scan(const int* __restrict__ labels) {
    __shared__ int sd[1024];
    int t = threadIdx.x;
    int base = t * 4;
    int z[4]; int cnt = 0;
#pragma unroll
    for (int u = 0; u < 4; u++) { z[u] = (labels[base + u] == 0) ? 1 : 0; cnt += z[u]; }
    sd[t] = cnt;
    __syncthreads();
    for (int off = 1; off < 1024; off <<= 1) {
        int v = (t >= off) ? sd[t - off] : 0;
        __syncthreads();
        sd[t] += v;
        __syncthreads();
    }
    int n0 = sd[1023];
    int zb = sd[t] - cnt;
#pragma unroll
    for (int u = 0; u < 4; u++) {
        int i = base + u, dest;
        if (z[u]) { dest = zb; zb++; }
        else      { dest = n0 + (i - zb); }
        g_src[dest] = i;
    }
    if (t == 0) g_n0 = n0;
}

// ---------------- 2. gather + L2-normalize + tf32-round ----------------
__global__ void k_norm(const float* __restrict__ proj) {
    int warp = (blockIdx.x * blockDim.x + threadIdx.x) >> 5;
    int lane = threadIdx.x & 31;
    if (warp >= B) return;
    int src = g_src[warp];
    const float* row = proj + src * D;
    float v[8]; float ss = 0.f;
#pragma unroll
    for (int u = 0; u < 8; u++) { v[u] = row[lane + u * 32]; ss += v[u] * v[u]; }
#pragma unroll
    for (int o = 16; o > 0; o >>= 1) ss += __shfl_xor_sync(0xffffffffu, ss, o);
    float inv = 1.0f / fmaxf(sqrtf(ss), 1e-12f);
    float* out = g_Ps + warp * D;
#pragma unroll
    for (int u = 0; u < 8; u++) out[lane + u * 32] = round_tf32(v[u] * inv);
}

// ---------------- 3. cross tiles: row/col sums of exp(sim/T) over neg pairs ----
__global__ void __launch_bounds__(256, 2) k_cross_mm() {
    extern __shared__ char sm[];
    int by = blockIdx.y, bx = blockIdx.x;
    int row0 = by * 128, col0 = bx * 128;
    int n0 = g_n0;
    if (!(row0 < n0 && col0 + 127 >= n0)) return;   // no (r<n0, c>=n0) pair here

    float acc[2][8][4];
    gemm_tile(sm, smem_u32(sm), row0, col0, acc);

    int t = threadIdx.x;
    int w = t >> 5, l = t & 31;
    int wm = w & 3, wn = w >> 2;
    int g = l >> 2, tg = l & 3;

    float rowp[2][2] = {{0.f,0.f},{0.f,0.f}};
    float colp[8][2];
#pragma unroll
    for (int nt = 0; nt < 8; nt++) { colp[nt][0] = 0.f; colp[nt][1] = 0.f; }
#pragma unroll
    for (int mt = 0; mt < 2; mt++) {
        int r0 = row0 + wm * 32 + mt * 16 + g;
        int r1 = r0 + 8;
        bool ga = (r0 < n0), gb = (r1 < n0);
#pragma unroll
        for (int nt = 0; nt < 8; nt++) {
            int c0 = col0 + wn * 64 + nt * 8 + tg * 2;
            bool ca = (c0 < n0), cb = (c0 + 1 < n0);
            float e00 = (ga != ca) ? expf(acc[mt][nt][0] * 10.0f) : 0.f;
            float e01 = (ga != cb) ? expf(acc[mt][nt][1] * 10.0f) : 0.f;
            float e10 = (gb != ca) ? expf(acc[mt][nt][2] * 10.0f) : 0.f;
            float e11 = (gb != cb) ? expf(acc[mt][nt][3] * 10.0f) : 0.f;
            rowp[mt][0] += e00 + e01;
            rowp[mt][1] += e10 + e11;
            colp[nt][0] += e00 + e10;
            colp[nt][1] += e01 + e11;
        }
    }
    // reduce rows over tg (quad), cols over g
#pragma unroll
    for (int mt = 0; mt < 2; mt++)
#pragma unroll
        for (int h = 0; h < 2; h++) {
            rowp[mt][h] += __shfl_xor_sync(0xffffffffu, rowp[mt][h], 1);
            rowp[mt][h] += __shfl_xor_sync(0xffffffffu, rowp[mt][h], 2);
        }
#pragma unroll
    for (int nt = 0; nt < 8; nt++)
#pragma unroll
        for (int h = 0; h < 2; h++) {
            colp[nt][h] += __shfl_xor_sync(0xffffffffu, colp[nt][h], 4);
            colp[nt][h] += __shfl_xor_sync(0xffffffffu, colp[nt][h], 8);
            colp[nt][h] += __shfl_xor_sync(0xffffffffu, colp[nt][h], 16);
        }
    float* rowred = (float*)sm;            // [2][128]
    float* colred = (float*)(sm + 1024);   // [4][128]
    if (tg == 0) {
#pragma unroll
        for (int mt = 0; mt < 2; mt++) {
            rowred[wn * 128 + wm * 32 + mt * 16 + g]     = rowp[mt][0];
            rowred[wn * 128 + wm * 32 + mt * 16 + g + 8] = rowp[mt][1];
        }
    }
    if (l < 4) {
#pragma unroll
        for (int nt = 0; nt < 8; nt++)
#pragma unroll
            for (int h = 0; h < 2; h++)
                colred[wm * 128 + wn * 64 + nt * 8 + l * 2 + h] = colp[nt][h];
    }
    __syncthreads();
    if (t < 128) {
        float rs = rowred[t] + rowred[128 + t];
        float cs = colred[t] + colred[128 + t] + colred[256 + t] + colred[384 + t];
        int r = row0 + t, c = col0 + t;
        if (r < n0)  g_RP[r * NT + bx] = rs;
        if (c >= n0) g_RP[c * NT + by] = cs;
    }
}

// ---------------- 4. L[i] = log(sum over written tile-partials) ----------------
__global__ void k_L() {
    int i = blockIdx.x * blockDim.x + threadIdx.x;
    int n0 = g_n0;
    int lo, hi;
    if (i < n0) { lo = n0 >> 7; hi = 31; }
    else        { lo = 0; hi = (n0 - 1) >> 7; }
    float s = 0.f;
    for (int q = lo; q <= hi; q++) s += g_RP[i * NT + q];
    g_L[i] = logf(s);
}

// ---------------- 5. within tiles: sum softplus(L - sim/T) over pos pairs -------
__global__ void __launch_bounds__(256, 2) k_within_mm() {
    extern __shared__ char sm[];
    int by = blockIdx.y, bx = blockIdx.x;
    int pidx = by * NT + bx;
    int row0 = by * 128, col0 = bx * 128;
    int n0 = g_n0;
    bool active = (bx >= by) && !((row0 + 127 < n0) && (col0 >= n0));
    if (!active) { if (threadIdx.x == 0) g_part2[pidx] = 0.f; return; }

    float acc[2][8][4];
    gemm_tile(sm, smem_u32(sm), row0, col0, acc);

    int t = threadIdx.x;
    int w = t >> 5, l = t & 31;
    int wm = w & 3, wn = w >> 2;
    int g = l >> 2, tg = l & 3;
    bool offd = (bx > by);

    float Lr[2][2], Lc[8][2];
#pragma unroll
    for (int mt = 0; mt < 2; mt++) {
        int r0 = row0 + wm * 32 + mt * 16 + g;
        Lr[mt][0] = g_L[r0];
        Lr[mt][1] = g_L[r0 + 8];
    }
#pragma unroll
    for (int nt = 0; nt < 8; nt++) {
        int c0 = col0 + wn * 64 + nt * 8 + tg * 2;
        Lc[nt][0] = g_L[c0];
        Lc[nt][1] = g_L[c0 + 1];
    }
    float local = 0.f;
#pragma unroll
    for (int mt = 0; mt < 2; mt++) {
        int r0 = row0 + wm * 32 + mt * 16 + g;
#pragma unroll
        for (int nt = 0; nt < 8; nt++) {
            int c0 = col0 + wn * 64 + nt * 8 + tg * 2;
#pragma unroll
            for (int e = 0; e < 4; e++) {
                int r = r0 + (e >> 1) * 8;
                int c = c0 + (e & 1);
                if (((r < n0) == (c < n0)) && (r != c)) {
                    float s10 = acc[mt][nt][e] * 10.0f;
                    local += log1pf(expf(Lr[mt][e >> 1] - s10));
                    if (offd) local += log1pf(expf(Lc[nt][e & 1] - s10));
                }
            }
        }
    }
    float* red = (float*)sm;
    red[t] = local;
    __syncthreads();
    for (int off = 128; off > 0; off >>= 1) { if (t < off) red[t] += red[t + off]; __syncthreads(); }
    if (t == 0) g_part2[pidx] = red[0];
}

// ---------------- 6. focal loss partials ----------------
__global__ void k_focal(const float* __restrict__ logits, const int* __restrict__ labels) {
    __shared__ float red[256];
    int t = threadIdx.x;
    int i = blockIdx.x * 256 + t;
    float z0 = logits[2 * i] / 1.5f;
    float z1 = logits[2 * i + 1] / 1.5f;
    float m = fmaxf(z0, z1);
    float lse = m + logf(expf(z0 - m) + expf(z1 - m));
    float ce = lse - (labels[i] ? z1 : z0);
    float pt = expf(-ce);
    float om = 1.0f - pt;
    red[t] = om * om * ce;
    __syncthreads();
    for (int off = 128; off > 0; off >>= 1) { if (t < off) red[t] += red[t + off]; __syncthreads(); }
    if (t == 0) g_part_focal[blockIdx.x] = red[0];
}

// ---------------- 7. region loss partials ----------------
__global__ void k_region(const float* __restrict__ rp, const int* __restrict__ labels) {
    __shared__ float red[16][128];
    int t = threadIdx.x;
    int b = blockIdx.x * 128 + t;
    float acc[16];
#pragma unroll
    for (int k = 0; k < 16; k++) acc[k] = 0.f;
    {
        int lab = labels[b];
        float p[4][2], lp[4][2], lpe[4][2], ent[4];
#pragma unroll
        for (int i = 0; i < 4; i++) {
            float x0 = rp[(i * B + b) * 2 + 0];
            float x1 = rp[(i * B + b) * 2 + 1];
            float m = fmaxf(x0, x1);
            float lse = m + logf(expf(x0 - m) + expf(x1 - m));
            lp[i][0] = x0 - lse; lp[i][1] = x1 - lse;
            p[i][0] = expf(lp[i][0]); p[i][1] = expf(lp[i][1]);
            lpe[i][0] = logf(p[i][0] + 1e-10f);
            lpe[i][1] = logf(p[i][1] + 1e-10f);
            ent[i] = p[i][0] * lp[i][0] + p[i][1] * lp[i][1];
            acc[12 + i] += -(lab ? lp[i][1] : lp[i][0]);
        }
        int pi = 0;
#pragma unroll
        for (int i = 0; i < 4; i++)
#pragma unroll
            for (int j = i + 1; j < 4; j++, pi++) {
                float kl = ent[j] - (p[j][0] * lpe[i][0] + p[j][1] * lpe[i][1]);
                if (lab) acc[pi] += kl; else acc[6 + pi] += kl;
            }
    }
#pragma unroll
    for (int k = 0; k < 16; k++) red[k][t] = acc[k];
    __syncthreads();
    for (int off = 64; off > 0; off >>= 1) {
        if (t < off) {
#pragma unroll
            for (int k = 0; k < 16; k++) red[k][t] += red[k][t + off];
        }
        __syncthreads();
    }
    if (t < 16) g_part_region[blockIdx.x * 16 + t] = red[t][0];
}

// ---------------- 8. final combine ----------------
__global__ void k_final(float* __restrict__ out) {
    __shared__ float red[256];
    __shared__ float sreg[16];
    __shared__ float sfoc;
    int t = threadIdx.x;
    float s = 0.f;
    for (int i = t; i < NT * NT; i += 256) s += g_part2[i];
    red[t] = s; __syncthreads();
    for (int off = 128; off > 0; off >>= 1) { if (t < off) red[t] += red[t + off]; __syncthreads(); }
    if (t < 16) {
        float a = 0.f;
        for (int blk = 0; blk < 32; blk++) a += g_part_region[blk * 16 + t];
        sreg[t] = a;
    }
    if (t == 16) {
        float f = 0.f;
        for (int i = 0; i < 16; i++) f += g_part_focal[i];
        sfoc = f;
    }
    __syncthreads();
    if (t == 0) {
        int n0 = g_n0;
        float cont = red[0] / (float)B;
        float foc = sfoc / (float)B;
        float pd = (float)(B - n0), ct = (float)n0;
        float rl = 0.f;
        for (int pi = 0; pi < 6; pi++) {
            float kpd = (pd > 0.f) ? sreg[pi]     / fmaxf(pd, 1.f) : 0.f;
            float kct = (ct > 0.f) ? sreg[6 + pi] / fmaxf(ct, 1.f) : 0.f;
            rl += kpd + kct;
        }
        for (int i = 0; i < 4; i++) rl += sreg[12 + i] / (float)B;
        rl /= 10.0f;                     // R*(R-1)/2 + R = 6 + 4
        out[0] = foc + 0.5f * cont + 0.3f * rl;
    }
}

// ---------------- launch ----------------
extern "C" void kernel_launch(void* const* d_in, const int* in_sizes, int n_in,
                              void* d_out, int out_size) {
    const float* logits = nullptr;
    const float* proj   = nullptr;
    const float* rp     = nullptr;
    const int*   labels = nullptr;
    for (int i = 0; i < n_in; i++) {
        switch (in_sizes[i]) {
            case B * 2:        logits = (const float*)d_in[i]; break;
            case B * D:        proj   = (const float*)d_in[i]; break;
            case 4 * B * 2:    rp     = (const float*)d_in[i]; break;
            case B:            labels = (const int*)d_in[i];   break;
        }
    }
    cudaFuncSetAttribute(k_cross_mm,  cudaFuncAttributeMaxDynamicSharedMemorySize, SMEM_BYTES);
    cudaFuncSetAttribute(k_within_mm, cudaFuncAttributeMaxDynamicSharedMemorySize, SMEM_BYTES);

    k_scan<<<1, 1024>>>(labels);
    k_norm<<<512, 256>>>(proj);
    dim3 g(NT, NT);
    k_cross_mm<<<g, 256, SMEM_BYTES>>>();
    k_L<<<16, 256>>>();
    k_within_mm<<<g, 256, SMEM_BYTES>>>();
    k_focal<<<16, 256>>>(logits, labels);
    k_region<<<32, 128>>>(rp, labels);
    k_final<<<1, 256>>>((float*)d_out);
}